// round 1
// baseline (speedup 1.0000x reference)
#include <cuda_runtime.h>
#include <cstdint>

// ---------------------------------------------------------------------------
// ANI AEV (radial + angular) scatter build.
// out layout per atom row (1008 fp32): [ S*NRBF radial (112) | NPAIRS*SUB angular (896) ]
// ---------------------------------------------------------------------------

#define S_       7
#define NRBF_    16
#define NPAIRS_  28
#define SUB_     32
#define NA_      8
#define NZ_      4
#define RC_      0.51f
#define RMIN_    0.08f
#define RCA_     0.35f
#define RAMIN_   0.08f
#define ETA_R_   1970.0f
#define ETA_A_   1250.0f
#define ZETA_    14.1f
#define ROW_     1008      // S_*NRBF_ + NPAIRS_*SUB_
#define ANG_OFF_ 112       // S_*NRBF_
#define PI_      3.14159265358979323846f

// sm_90+ vector reduction: one instruction adds 4 contiguous fp32 in L2.
__device__ __forceinline__ void red_add_v4(float* addr, float a, float b, float c, float d) {
    asm volatile("red.global.add.v4.f32 [%0], {%1, %2, %3, %4};"
                 :: "l"(addr), "f"(a), "f"(b), "f"(c), "f"(d)
                 : "memory");
}

// ---------------------------------------------------------------------------
// Radial: one thread per pair. 16 RBF terms scattered to both endpoint atoms.
// ---------------------------------------------------------------------------
__global__ void __launch_bounds__(256)
radial_kernel(const int* __restrict__ atom_index,
              const int* __restrict__ pair_idx,   // [2, P]
              const float* __restrict__ d_ij,     // [P]
              float* __restrict__ out,
              int P)
{
    int p = blockIdx.x * blockDim.x + threadIdx.x;
    if (p >= P) return;

    float d  = d_ij[p];
    int   i  = pair_idx[p];
    int   j  = pair_idx[P + p];
    int   si = atom_index[i];
    int   sj = atom_index[j];

    float fc = (d < RC_) ? (0.5f * __cosf(PI_ * d * (1.0f / RC_)) + 0.5f) : 0.0f;
    float amp = 0.25f * fc;

    const float step = (RC_ - RMIN_) / (float)NRBF_;   // 0.026875
    float t[NRBF_];
#pragma unroll
    for (int k = 0; k < NRBF_; k++) {
        float x = d - (RMIN_ + (float)k * step);
        t[k] = amp * __expf(-ETA_R_ * x * x);
    }

    float* r0 = out + (long long)i * ROW_ + sj * NRBF_;
    float* r1 = out + (long long)j * ROW_ + si * NRBF_;
#pragma unroll
    for (int q = 0; q < 4; q++)
        red_add_v4(r0 + 4 * q, t[4*q], t[4*q+1], t[4*q+2], t[4*q+3]);
#pragma unroll
    for (int q = 0; q < 4; q++)
        red_add_v4(r1 + 4 * q, t[4*q], t[4*q+1], t[4*q+2], t[4*q+3]);
}

// ---------------------------------------------------------------------------
// Angular: one thread per triple. 8x4 terms scattered to the central atom's
// (species-pair) block. Uses cos(angle - shfz) = cos_a*cz + sin_a*sz to avoid
// arccos entirely (exact identity for angle in [0, pi]).
// ---------------------------------------------------------------------------
__global__ void __launch_bounds__(256)
angular_kernel(const int* __restrict__ atom_index,
               const int* __restrict__ pair_idx,    // [2, P]
               const float* __restrict__ r_ij,      // [P, 3]
               const int* __restrict__ central,     // [T]
               const int* __restrict__ pidx12,      // [2, T]
               const int* __restrict__ sign12,      // [2, T]
               float* __restrict__ out,
               int P, int T)
{
    int t = blockIdx.x * blockDim.x + threadIdx.x;
    if (t >= T) return;

    int c  = central[t];
    int p0 = pidx12[t];
    int p1 = pidx12[T + t];
    int g0 = sign12[t];
    int g1 = sign12[T + t];

    float s0f = (float)g0, s1f = (float)g1;
    float v0x = r_ij[3*p0 + 0] * s0f, v0y = r_ij[3*p0 + 1] * s0f, v0z = r_ij[3*p0 + 2] * s0f;
    float v1x = r_ij[3*p1 + 0] * s1f, v1y = r_ij[3*p1 + 1] * s1f, v1z = r_ij[3*p1 + 2] * s1f;

    float d0 = sqrtf(v0x*v0x + v0y*v0y + v0z*v0z);
    float d1 = sqrtf(v1x*v1x + v1y*v1y + v1z*v1z);
    float dot01 = v0x*v1x + v0y*v1y + v0z*v1z;

    float cos_a = 0.95f * dot01 / (d0 * d1);
    float sin_a = sqrtf(fmaxf(1.0f - cos_a * cos_a, 0.0f));

    float fc0 = (d0 < RCA_) ? (0.5f * __cosf(PI_ * d0 * (1.0f / RCA_)) + 0.5f) : 0.0f;
    float fc1 = (d1 < RCA_) ? (0.5f * __cosf(PI_ * d1 * (1.0f / RCA_)) + 0.5f) : 0.0f;
    float fcp = 2.0f * fc0 * fc1;
    float davg = 0.5f * (d0 + d1);

    // species of the two neighbor atoms
    int sp0 = atom_index[(g0 == 1) ? pair_idx[P + p0] : pair_idx[p0]];
    int sp1 = atom_index[(g1 == 1) ? pair_idx[P + p1] : pair_idx[p1]];
    int a = min(sp0, sp1), b = max(sp0, sp1);
    int triu = a * S_ - (a * (a - 1)) / 2 + (b - a);

    // f1[z] = ((1 + cos(angle - shfz_z)) / 2)^ZETA
    // shfz = (z + 0.5) * pi/4 -> precomputed cos/sin
    const float cz0 =  0.9238795325112867f, sz0 = 0.3826834323650898f; // pi/8
    const float cz1 =  0.3826834323650898f, sz1 = 0.9238795325112867f; // 3pi/8
    const float cz2 = -0.3826834323650898f, sz2 = 0.9238795325112867f; // 5pi/8
    const float cz3 = -0.9238795325112867f, sz3 = 0.3826834323650898f; // 7pi/8

    float f1[NZ_];
    {
        float x0 = fmaxf(0.5f * (1.0f + cos_a * cz0 + sin_a * sz0), 0.0f);
        float x1 = fmaxf(0.5f * (1.0f + cos_a * cz1 + sin_a * sz1), 0.0f);
        float x2 = fmaxf(0.5f * (1.0f + cos_a * cz2 + sin_a * sz2), 0.0f);
        float x3 = fmaxf(0.5f * (1.0f + cos_a * cz3 + sin_a * sz3), 0.0f);
        f1[0] = __powf(x0, ZETA_);
        f1[1] = __powf(x1, ZETA_);
        f1[2] = __powf(x2, ZETA_);
        f1[3] = __powf(x3, ZETA_);
    }

    float* dst = out + (long long)c * ROW_ + ANG_OFF_ + triu * SUB_;

    const float step_a = (RCA_ - RAMIN_) / (float)NA_;   // 0.03375
#pragma unroll
    for (int k = 0; k < NA_; k++) {
        float y = davg - (RAMIN_ + (float)k * step_a);
        float f2 = fcp * __expf(-ETA_A_ * y * y);
        red_add_v4(dst + 4 * k, f2 * f1[0], f2 * f1[1], f2 * f1[2], f2 * f1[3]);
    }
}

// ---------------------------------------------------------------------------
// Launch
// Inputs (metadata order):
//  0: atom_index  int32 [N]
//  1: pair_indices int32 [2, P]
//  2: d_ij        f32 [P, 1]
//  3: r_ij        f32 [P, 3]
//  4: central_atom_index int32 [T]
//  5: pair_index12 int32 [2, T]
//  6: sign12      int32 [2, T]
// Output: f32 [N, 1008]
// ---------------------------------------------------------------------------
extern "C" void kernel_launch(void* const* d_in, const int* in_sizes, int n_in,
                              void* d_out, int out_size)
{
    const int*   atom_index = (const int*)d_in[0];
    const int*   pair_idx   = (const int*)d_in[1];
    const float* d_ij       = (const float*)d_in[2];
    const float* r_ij       = (const float*)d_in[3];
    const int*   central    = (const int*)d_in[4];
    const int*   pidx12     = (const int*)d_in[5];
    const int*   sign12     = (const int*)d_in[6];
    float*       out        = (float*)d_out;

    int P = in_sizes[2];        // d_ij element count
    int T = in_sizes[4];        // number of triples

    cudaMemsetAsync(out, 0, (size_t)out_size * sizeof(float));

    {
        int threads = 256;
        int blocks = (P + threads - 1) / threads;
        radial_kernel<<<blocks, threads>>>(atom_index, pair_idx, d_ij, out, P);
    }
    {
        int threads = 256;
        int blocks = (T + threads - 1) / threads;
        angular_kernel<<<blocks, threads>>>(atom_index, pair_idx, r_ij,
                                            central, pidx12, sign12, out, P, T);
    }
}

// round 2
// speedup vs baseline: 1.3683x; 1.3683x over previous
#include <cuda_runtime.h>
#include <cstdint>

// ---------------------------------------------------------------------------
// ANI AEV (radial + angular) scatter build, round 1:
//  - Gaussian sparsity: skip red.v4 groups whose exp() terms are < ~1e-5
//  - angular pair precompute: aligned float4 {r_ij, d} + packed species,
//    removes dependent gather chain, sqrt, and unaligned 12B loads
// ---------------------------------------------------------------------------

#define S_       7
#define NRBF_    16
#define NPAIRS_  28
#define SUB_     32
#define NA_      8
#define NZ_      4
#define RC_      0.51f
#define RMIN_    0.08f
#define RCA_     0.35f
#define RAMIN_   0.08f
#define ETA_R_   1970.0f
#define ETA_A_   1250.0f
#define ZETA_    14.1f
#define ROW_     1008      // S_*NRBF_ + NPAIRS_*SUB_
#define ANG_OFF_ 112       // S_*NRBF_
#define PI_      3.14159265358979323846f
#define PA_MAX_  200000

// scratch (device globals: no allocation allowed)
__device__ float4 g_pv[PA_MAX_];   // {rx, ry, rz, d}
__device__ int    g_psp[PA_MAX_];  // species_i | species_j << 8

// sm_90+ vector reduction: one instruction adds 4 contiguous fp32 in L2.
__device__ __forceinline__ void red_add_v4(float* addr, float a, float b, float c, float d) {
    asm volatile("red.global.add.v4.f32 [%0], {%1, %2, %3, %4};"
                 :: "l"(addr), "f"(a), "f"(b), "f"(c), "f"(d)
                 : "memory");
}

// ---------------------------------------------------------------------------
// Prep: pack per-pair data for the angular kernel (pairs [0, PA)).
// ---------------------------------------------------------------------------
__global__ void __launch_bounds__(256)
prep_kernel(const int* __restrict__ atom_index,
            const int* __restrict__ pair_idx,   // [2, P]
            const float* __restrict__ d_ij,     // [P]
            const float* __restrict__ r_ij,     // [P, 3]
            int P, int PA)
{
    int p = blockIdx.x * blockDim.x + threadIdx.x;
    if (p >= PA) return;
    float rx = r_ij[3*p + 0], ry = r_ij[3*p + 1], rz = r_ij[3*p + 2];
    g_pv[p] = make_float4(rx, ry, rz, d_ij[p]);
    int si = atom_index[pair_idx[p]];
    int sj = atom_index[pair_idx[P + p]];
    g_psp[p] = si | (sj << 8);
}

// ---------------------------------------------------------------------------
// Radial: one thread per pair. 16 RBF terms scattered to both endpoint atoms.
// Only v4 groups with non-negligible Gaussians are emitted.
// ---------------------------------------------------------------------------
__global__ void __launch_bounds__(256)
radial_kernel(const int* __restrict__ atom_index,
              const int* __restrict__ pair_idx,   // [2, P]
              const float* __restrict__ d_ij,     // [P]
              float* __restrict__ out,
              int P)
{
    int p = blockIdx.x * blockDim.x + threadIdx.x;
    if (p >= P) return;

    float d  = d_ij[p];
    int   i  = pair_idx[p];
    int   j  = pair_idx[P + p];
    int   si = atom_index[i];
    int   sj = atom_index[j];

    float fc = (d < RC_) ? (0.5f * __cosf(PI_ * d * (1.0f / RC_)) + 0.5f) : 0.0f;
    float amp = 0.25f * fc;

    const float step = (RC_ - RMIN_) / (float)NRBF_;   // 0.026875

    float* r0 = out + (long long)i * ROW_ + sj * NRBF_;
    float* r1 = out + (long long)j * ROW_ + si * NRBF_;

#pragma unroll
    for (int q = 0; q < 4; q++) {
        // distance from d to the center interval of this group of 4
        float lo = RMIN_ + (float)(4*q) * step;
        float hi = lo + 3.0f * step;
        float dist = fmaxf(fmaxf(lo - d, d - hi), 0.0f);
        // exp(-1970 * 0.078^2) ~= 6e-6: below threshold, all 4 terms negligible
        if (dist < 0.078f) {
            float x0 = d - lo;
            float x1 = x0 - step;
            float x2 = x1 - step;
            float x3 = x2 - step;
            float t0 = amp * __expf(-ETA_R_ * x0 * x0);
            float t1 = amp * __expf(-ETA_R_ * x1 * x1);
            float t2 = amp * __expf(-ETA_R_ * x2 * x2);
            float t3 = amp * __expf(-ETA_R_ * x3 * x3);
            red_add_v4(r0 + 4*q, t0, t1, t2, t3);
            red_add_v4(r1 + 4*q, t0, t1, t2, t3);
        }
    }
}

// ---------------------------------------------------------------------------
// Angular: one thread per triple, reading the packed per-pair data.
// cos(angle - shfz) = cos_a*cz + sin_a*sz (identity, no arccos).
// d12 = |r_ij * sign| = d_ij (norm is sign-invariant); dot picks up g0*g1.
// ---------------------------------------------------------------------------
__global__ void __launch_bounds__(256)
angular_kernel(const int* __restrict__ central,     // [T]
               const int* __restrict__ pidx12,      // [2, T]
               const int* __restrict__ sign12,      // [2, T]
               float* __restrict__ out,
               int T)
{
    int t = blockIdx.x * blockDim.x + threadIdx.x;
    if (t >= T) return;

    int c  = central[t];
    int p0 = pidx12[t];
    int p1 = pidx12[T + t];
    int g0 = sign12[t];
    int g1 = sign12[T + t];

    float4 a0 = g_pv[p0];
    float4 a1 = g_pv[p1];
    int   q0 = g_psp[p0];
    int   q1 = g_psp[p1];

    float d0 = a0.w, d1 = a1.w;
    float dot = a0.x*a1.x + a0.y*a1.y + a0.z*a1.z;
    float sgn = (float)(g0 * g1);

    float cos_a = 0.95f * sgn * dot / (d0 * d1);
    float sin_a = sqrtf(fmaxf(1.0f - cos_a * cos_a, 0.0f));

    float fc0 = (d0 < RCA_) ? (0.5f * __cosf(PI_ * d0 * (1.0f / RCA_)) + 0.5f) : 0.0f;
    float fc1 = (d1 < RCA_) ? (0.5f * __cosf(PI_ * d1 * (1.0f / RCA_)) + 0.5f) : 0.0f;
    float fcp = 2.0f * fc0 * fc1;
    float davg = 0.5f * (d0 + d1);

    // neighbor species: sign==+1 -> species of j, else species of i
    int sp0 = (g0 == 1) ? (q0 >> 8) : (q0 & 255);
    int sp1 = (g1 == 1) ? (q1 >> 8) : (q1 & 255);
    int a = min(sp0, sp1), b = max(sp0, sp1);
    int triu = a * S_ - (a * (a - 1)) / 2 + (b - a);

    // f1[z] = ((1 + cos(angle - shfz_z)) / 2)^ZETA,  shfz = (z+0.5)*pi/4
    const float cz0 =  0.9238795325112867f, sz0 = 0.3826834323650898f;
    const float cz1 =  0.3826834323650898f, sz1 = 0.9238795325112867f;
    const float cz2 = -0.3826834323650898f, sz2 = 0.9238795325112867f;
    const float cz3 = -0.9238795325112867f, sz3 = 0.3826834323650898f;

    float f10 = __powf(fmaxf(0.5f * (1.0f + cos_a * cz0 + sin_a * sz0), 0.0f), ZETA_);
    float f11 = __powf(fmaxf(0.5f * (1.0f + cos_a * cz1 + sin_a * sz1), 0.0f), ZETA_);
    float f12 = __powf(fmaxf(0.5f * (1.0f + cos_a * cz2 + sin_a * sz2), 0.0f), ZETA_);
    float f13 = __powf(fmaxf(0.5f * (1.0f + cos_a * cz3 + sin_a * sz3), 0.0f), ZETA_);

    float* dst = out + (long long)c * ROW_ + ANG_OFF_ + triu * SUB_;

    const float step_a = (RCA_ - RAMIN_) / (float)NA_;   // 0.03375
#pragma unroll
    for (int k = 0; k < NA_; k++) {
        float y = davg - (RAMIN_ + (float)k * step_a);
        float arg = ETA_A_ * y * y;
        // exp(-10) ~= 4.5e-5: below threshold the 4 terms are negligible
        if (arg < 10.0f) {
            float f2 = fcp * __expf(-arg);
            red_add_v4(dst + 4*k, f2 * f10, f2 * f11, f2 * f12, f2 * f13);
        }
    }
}

// ---------------------------------------------------------------------------
// Launch.  Inputs (metadata order):
//  0: atom_index int32[N]  1: pair_indices int32[2,P]  2: d_ij f32[P,1]
//  3: r_ij f32[P,3]  4: central int32[T]  5: pair_index12 int32[2,T]
//  6: sign12 int32[2,T]      Output: f32 [N, 1008]
// ---------------------------------------------------------------------------
extern "C" void kernel_launch(void* const* d_in, const int* in_sizes, int n_in,
                              void* d_out, int out_size)
{
    const int*   atom_index = (const int*)d_in[0];
    const int*   pair_idx   = (const int*)d_in[1];
    const float* d_ij       = (const float*)d_in[2];
    const float* r_ij       = (const float*)d_in[3];
    const int*   central    = (const int*)d_in[4];
    const int*   pidx12     = (const int*)d_in[5];
    const int*   sign12     = (const int*)d_in[6];
    float*       out        = (float*)d_out;

    int P = in_sizes[2];
    int T = in_sizes[4];
    int PA = P < PA_MAX_ ? P : PA_MAX_;   // triples only reference pairs < PA

    cudaMemsetAsync(out, 0, (size_t)out_size * sizeof(float));

    {
        int threads = 256;
        prep_kernel<<<(PA + threads - 1) / threads, threads>>>(
            atom_index, pair_idx, d_ij, r_ij, P, PA);
    }
    {
        int threads = 256;
        radial_kernel<<<(P + threads - 1) / threads, threads>>>(
            atom_index, pair_idx, d_ij, out, P);
    }
    {
        int threads = 256;
        angular_kernel<<<(T + threads - 1) / threads, threads>>>(
            central, pidx12, sign12, out, T);
    }
}

// round 3
// speedup vs baseline: 1.4170x; 1.0356x over previous
#include <cuda_runtime.h>
#include <cstdint>

// ---------------------------------------------------------------------------
// ANI AEV scatter build, round 2:
//  - kernel 1: fused zero-fill(out) + pair precompute (disjoint resources)
//  - kernel 2: fused radial + angular scatter (both L2-red-bound, disjoint
//    output regions, run concurrently via block-range split)
// ---------------------------------------------------------------------------

#define S_       7
#define NRBF_    16
#define NPAIRS_  28
#define SUB_     32
#define NA_      8
#define NZ_      4
#define RC_      0.51f
#define RMIN_    0.08f
#define RCA_     0.35f
#define RAMIN_   0.08f
#define ETA_R_   1970.0f
#define ETA_A_   1250.0f
#define ZETA_    14.1f
#define ROW_     1008      // S_*NRBF_ + NPAIRS_*SUB_
#define ANG_OFF_ 112       // S_*NRBF_
#define PI_      3.14159265358979323846f
#define PA_MAX_  200000

#define THREADS_ 256
#define ZERO_BLOCKS_ 2048

// scratch (device globals: no allocation allowed)
__device__ float4 g_pv[PA_MAX_];   // {rx, ry, rz, d}
__device__ int    g_psp[PA_MAX_];  // species_i | species_j << 8

// sm_90+ vector reduction: one instruction adds 4 contiguous fp32 in L2.
__device__ __forceinline__ void red_add_v4(float* addr, float a, float b, float c, float d) {
    asm volatile("red.global.add.v4.f32 [%0], {%1, %2, %3, %4};"
                 :: "l"(addr), "f"(a), "f"(b), "f"(c), "f"(d)
                 : "memory");
}

// ---------------------------------------------------------------------------
// Phase 1: blocks [0, prep_blocks) pack per-pair data; the rest zero `out`.
// ---------------------------------------------------------------------------
__global__ void __launch_bounds__(THREADS_)
zero_prep_kernel(const int* __restrict__ atom_index,
                 const int* __restrict__ pair_idx,   // [2, P]
                 const float* __restrict__ d_ij,     // [P]
                 const float* __restrict__ r_ij,     // [P, 3]
                 float* __restrict__ out,
                 int P, int PA, int prep_blocks, long long out_elems)
{
    if ((int)blockIdx.x < prep_blocks) {
        int p = blockIdx.x * THREADS_ + threadIdx.x;
        if (p >= PA) return;
        float rx = r_ij[3*p + 0], ry = r_ij[3*p + 1], rz = r_ij[3*p + 2];
        g_pv[p] = make_float4(rx, ry, rz, d_ij[p]);
        int si = atom_index[pair_idx[p]];
        int sj = atom_index[pair_idx[P + p]];
        g_psp[p] = si | (sj << 8);
    } else {
        // grid-stride zero with 16B stores (out_elems is divisible by 4)
        long long nthreads = (long long)(gridDim.x - prep_blocks) * THREADS_;
        long long tid = (long long)((int)blockIdx.x - prep_blocks) * THREADS_ + threadIdx.x;
        float4* o4 = (float4*)out;
        long long n4 = out_elems >> 2;
        float4 z = make_float4(0.f, 0.f, 0.f, 0.f);
        for (long long q = tid; q < n4; q += nthreads)
            o4[q] = z;
    }
}

// ---------------------------------------------------------------------------
// Phase 2: blocks [0, ang_blocks) do angular triples; the rest radial pairs.
// ---------------------------------------------------------------------------
__device__ __forceinline__ void do_radial(const int* __restrict__ atom_index,
                                          const int* __restrict__ pair_idx,
                                          const float* __restrict__ d_ij,
                                          float* __restrict__ out,
                                          int P, int p)
{
    if (p >= P) return;

    float d  = d_ij[p];
    int   i  = pair_idx[p];
    int   j  = pair_idx[P + p];
    int   si = atom_index[i];
    int   sj = atom_index[j];

    float fc = (d < RC_) ? (0.5f * __cosf(PI_ * d * (1.0f / RC_)) + 0.5f) : 0.0f;
    float amp = 0.25f * fc;

    const float step = (RC_ - RMIN_) / (float)NRBF_;   // 0.026875

    float* r0 = out + (long long)i * ROW_ + sj * NRBF_;
    float* r1 = out + (long long)j * ROW_ + si * NRBF_;

#pragma unroll
    for (int q = 0; q < 4; q++) {
        float lo = RMIN_ + (float)(4*q) * step;
        float hi = lo + 3.0f * step;
        float dist = fmaxf(fmaxf(lo - d, d - hi), 0.0f);
        // exp(-1970 * 0.078^2) ~= 6e-6: below threshold all 4 terms negligible
        if (dist < 0.078f) {
            float x0 = d - lo;
            float x1 = x0 - step;
            float x2 = x1 - step;
            float x3 = x2 - step;
            float t0 = amp * __expf(-ETA_R_ * x0 * x0);
            float t1 = amp * __expf(-ETA_R_ * x1 * x1);
            float t2 = amp * __expf(-ETA_R_ * x2 * x2);
            float t3 = amp * __expf(-ETA_R_ * x3 * x3);
            red_add_v4(r0 + 4*q, t0, t1, t2, t3);
            red_add_v4(r1 + 4*q, t0, t1, t2, t3);
        }
    }
}

__device__ __forceinline__ void do_angular(const int* __restrict__ central,
                                           const int* __restrict__ pidx12,
                                           const int* __restrict__ sign12,
                                           float* __restrict__ out,
                                           int T, int t)
{
    if (t >= T) return;

    int c  = central[t];
    int p0 = pidx12[t];
    int p1 = pidx12[T + t];
    int g0 = sign12[t];
    int g1 = sign12[T + t];

    float4 a0 = g_pv[p0];
    float4 a1 = g_pv[p1];
    int   q0 = g_psp[p0];
    int   q1 = g_psp[p1];

    float d0 = a0.w, d1 = a1.w;
    float dot = a0.x*a1.x + a0.y*a1.y + a0.z*a1.z;
    float sgn = (float)(g0 * g1);

    float cos_a = __fdividef(0.95f * sgn * dot, d0 * d1);
    float sin_a = sqrtf(fmaxf(1.0f - cos_a * cos_a, 0.0f));

    float fc0 = (d0 < RCA_) ? (0.5f * __cosf(PI_ * d0 * (1.0f / RCA_)) + 0.5f) : 0.0f;
    float fc1 = (d1 < RCA_) ? (0.5f * __cosf(PI_ * d1 * (1.0f / RCA_)) + 0.5f) : 0.0f;
    float fcp = 2.0f * fc0 * fc1;
    float davg = 0.5f * (d0 + d1);

    int sp0 = (g0 == 1) ? (q0 >> 8) : (q0 & 255);
    int sp1 = (g1 == 1) ? (q1 >> 8) : (q1 & 255);
    int a = min(sp0, sp1), b = max(sp0, sp1);
    int triu = a * S_ - (a * (a - 1)) / 2 + (b - a);

    // f1[z] = ((1 + cos(angle - shfz_z)) / 2)^ZETA,  shfz = (z+0.5)*pi/4
    const float cz0 =  0.9238795325112867f, sz0 = 0.3826834323650898f;
    const float cz1 =  0.3826834323650898f, sz1 = 0.9238795325112867f;
    const float cz2 = -0.3826834323650898f, sz2 = 0.9238795325112867f;
    const float cz3 = -0.9238795325112867f, sz3 = 0.3826834323650898f;

    float f10 = __powf(fmaxf(0.5f * (1.0f + cos_a * cz0 + sin_a * sz0), 0.0f), ZETA_);
    float f11 = __powf(fmaxf(0.5f * (1.0f + cos_a * cz1 + sin_a * sz1), 0.0f), ZETA_);
    float f12 = __powf(fmaxf(0.5f * (1.0f + cos_a * cz2 + sin_a * sz2), 0.0f), ZETA_);
    float f13 = __powf(fmaxf(0.5f * (1.0f + cos_a * cz3 + sin_a * sz3), 0.0f), ZETA_);

    float* dst = out + (long long)c * ROW_ + ANG_OFF_ + triu * SUB_;

    const float step_a = (RCA_ - RAMIN_) / (float)NA_;   // 0.03375
#pragma unroll
    for (int k = 0; k < NA_; k++) {
        float y = davg - (RAMIN_ + (float)k * step_a);
        float arg = ETA_A_ * y * y;
        // exp(-10) ~= 4.5e-5: negligible below threshold
        if (arg < 10.0f) {
            float f2 = fcp * __expf(-arg);
            red_add_v4(dst + 4*k, f2 * f10, f2 * f11, f2 * f12, f2 * f13);
        }
    }
}

__global__ void __launch_bounds__(THREADS_)
scatter_kernel(const int* __restrict__ atom_index,
               const int* __restrict__ pair_idx,
               const float* __restrict__ d_ij,
               const int* __restrict__ central,
               const int* __restrict__ pidx12,
               const int* __restrict__ sign12,
               float* __restrict__ out,
               int P, int T, int ang_blocks)
{
    int b = (int)blockIdx.x;
    if (b < ang_blocks) {
        do_angular(central, pidx12, sign12, out, T,
                   b * THREADS_ + (int)threadIdx.x);
    } else {
        do_radial(atom_index, pair_idx, d_ij, out, P,
                  (b - ang_blocks) * THREADS_ + (int)threadIdx.x);
    }
}

// ---------------------------------------------------------------------------
// Launch.  Inputs (metadata order):
//  0: atom_index int32[N]  1: pair_indices int32[2,P]  2: d_ij f32[P,1]
//  3: r_ij f32[P,3]  4: central int32[T]  5: pair_index12 int32[2,T]
//  6: sign12 int32[2,T]      Output: f32 [N, 1008]
// ---------------------------------------------------------------------------
extern "C" void kernel_launch(void* const* d_in, const int* in_sizes, int n_in,
                              void* d_out, int out_size)
{
    const int*   atom_index = (const int*)d_in[0];
    const int*   pair_idx   = (const int*)d_in[1];
    const float* d_ij       = (const float*)d_in[2];
    const float* r_ij       = (const float*)d_in[3];
    const int*   central    = (const int*)d_in[4];
    const int*   pidx12     = (const int*)d_in[5];
    const int*   sign12     = (const int*)d_in[6];
    float*       out        = (float*)d_out;

    int P = in_sizes[2];
    int T = in_sizes[4];
    int PA = P < PA_MAX_ ? P : PA_MAX_;

    {
        int prep_blocks = (PA + THREADS_ - 1) / THREADS_;
        int grid = prep_blocks + ZERO_BLOCKS_;
        zero_prep_kernel<<<grid, THREADS_>>>(atom_index, pair_idx, d_ij, r_ij,
                                             out, P, PA, prep_blocks,
                                             (long long)out_size);
    }
    {
        int ang_blocks = (T + THREADS_ - 1) / THREADS_;
        int rad_blocks = (P + THREADS_ - 1) / THREADS_;
        scatter_kernel<<<ang_blocks + rad_blocks, THREADS_>>>(
            atom_index, pair_idx, d_ij, central, pidx12, sign12, out,
            P, T, ang_blocks);
    }
}

// round 7
// speedup vs baseline: 1.4767x; 1.0421x over previous
#include <cuda_runtime.h>
#include <cstdint>

// ---------------------------------------------------------------------------
// ANI AEV scatter build, round 4 (resubmit x2 — R5/R6 were infra timeouts):
//  - strictly serial, no stream/event creation (allocation-guard clean)
//  - prep packs {r_ij,d} float4 + {i|si<<17, j|sj<<17} int2 per pair
//  - angular derives sign12 and neighbor species from `central` comparison
//    (saves 2 LDG per triple); Gaussian sparsity thresholds 0.070 / 8.0
// ---------------------------------------------------------------------------

#define S_       7
#define NRBF_    16
#define NPAIRS_  28
#define SUB_     32
#define NA_      8
#define NZ_      4
#define RC_      0.51f
#define RMIN_    0.08f
#define RCA_     0.35f
#define RAMIN_   0.08f
#define ETA_R_   1970.0f
#define ETA_A_   1250.0f
#define ZETA_    14.1f
#define ROW_     1008      // S_*NRBF_ + NPAIRS_*SUB_
#define ANG_OFF_ 112       // S_*NRBF_
#define PI_      3.14159265358979323846f
#define PA_MAX_  200000

#define THREADS_ 256

// scratch (device globals: no allocation allowed)
__device__ float4 g_pv[PA_MAX_];    // {rx, ry, rz, d}
__device__ int2   g_pij[PA_MAX_];   // {i | si<<17, j | sj<<17}

// sm_90+ vector reduction: one instruction adds 4 contiguous fp32 in L2.
__device__ __forceinline__ void red_add_v4(float* addr, float a, float b, float c, float d) {
    asm volatile("red.global.add.v4.f32 [%0], {%1, %2, %3, %4};"
                 :: "l"(addr), "f"(a), "f"(b), "f"(c), "f"(d)
                 : "memory");
}

// ---------------------------------------------------------------------------
// Prep: pack per-pair data for the angular kernel (pairs [0, PA)).
// ---------------------------------------------------------------------------
__global__ void __launch_bounds__(THREADS_)
prep_kernel(const int* __restrict__ atom_index,
            const int* __restrict__ pair_idx,   // [2, P]
            const float* __restrict__ d_ij,     // [P]
            const float* __restrict__ r_ij,     // [P, 3]
            int P, int PA)
{
    int p = blockIdx.x * THREADS_ + threadIdx.x;
    if (p >= PA) return;
    float rx = r_ij[3*p + 0], ry = r_ij[3*p + 1], rz = r_ij[3*p + 2];
    g_pv[p] = make_float4(rx, ry, rz, d_ij[p]);
    int i = pair_idx[p];
    int j = pair_idx[P + p];
    int si = atom_index[i];
    int sj = atom_index[j];
    g_pij[p] = make_int2(i | (si << 17), j | (sj << 17));
}

// ---------------------------------------------------------------------------
// Radial part: one thread per pair.
// ---------------------------------------------------------------------------
__device__ __forceinline__ void do_radial(const int* __restrict__ atom_index,
                                          const int* __restrict__ pair_idx,
                                          const float* __restrict__ d_ij,
                                          float* __restrict__ out,
                                          int P, int p)
{
    if (p >= P) return;

    float d  = d_ij[p];
    int   i  = pair_idx[p];
    int   j  = pair_idx[P + p];
    int   si = atom_index[i];
    int   sj = atom_index[j];

    float fc = (d < RC_) ? (0.5f * __cosf(PI_ * d * (1.0f / RC_)) + 0.5f) : 0.0f;
    float amp = 0.25f * fc;

    const float step = (RC_ - RMIN_) / (float)NRBF_;   // 0.026875

    float* r0 = out + (long long)i * ROW_ + sj * NRBF_;
    float* r1 = out + (long long)j * ROW_ + si * NRBF_;

#pragma unroll
    for (int q = 0; q < 4; q++) {
        float lo = RMIN_ + (float)(4*q) * step;
        float hi = lo + 3.0f * step;
        float dist = fmaxf(fmaxf(lo - d, d - hi), 0.0f);
        // exp(-1970 * 0.070^2) ~= 6.4e-5: all 4 terms negligible beyond
        if (dist < 0.070f) {
            float x0 = d - lo;
            float x1 = x0 - step;
            float x2 = x1 - step;
            float x3 = x2 - step;
            float t0 = amp * __expf(-ETA_R_ * x0 * x0);
            float t1 = amp * __expf(-ETA_R_ * x1 * x1);
            float t2 = amp * __expf(-ETA_R_ * x2 * x2);
            float t3 = amp * __expf(-ETA_R_ * x3 * x3);
            red_add_v4(r0 + 4*q, t0, t1, t2, t3);
            red_add_v4(r1 + 4*q, t0, t1, t2, t3);
        }
    }
}

// ---------------------------------------------------------------------------
// Angular part: one thread per triple. sign12 / neighbor species derived from
// comparing `central` against the pair's endpoints (exact: endpoints differ).
// ---------------------------------------------------------------------------
__device__ __forceinline__ void do_angular(const int* __restrict__ central,
                                           const int* __restrict__ pidx12,
                                           float* __restrict__ out,
                                           int T, int t)
{
    if (t >= T) return;

    int c  = central[t];
    int p0 = pidx12[t];
    int p1 = pidx12[T + t];

    float4 a0 = g_pv[p0];
    float4 a1 = g_pv[p1];
    int2   e0 = g_pij[p0];
    int2   e1 = g_pij[p1];

    int i0 = e0.x & 0x1FFFF;
    int i1 = e1.x & 0x1FFFF;
    bool ci0 = (c == i0);           // sign12[0] == +1
    bool ci1 = (c == i1);           // sign12[1] == +1

    // neighbor species: +1 -> species of j endpoint, else species of i endpoint
    int sp0 = ci0 ? (e0.y >> 17) : (e0.x >> 17);
    int sp1 = ci1 ? (e1.y >> 17) : (e1.x >> 17);

    float d0 = a0.w, d1 = a1.w;
    float dot = a0.x*a1.x + a0.y*a1.y + a0.z*a1.z;
    float sgn = (ci0 == ci1) ? 1.0f : -1.0f;   // product of the two signs

    float cos_a = __fdividef(0.95f * sgn * dot, d0 * d1);
    float sin_a = sqrtf(fmaxf(1.0f - cos_a * cos_a, 0.0f));

    float fc0 = (d0 < RCA_) ? (0.5f * __cosf(PI_ * d0 * (1.0f / RCA_)) + 0.5f) : 0.0f;
    float fc1 = (d1 < RCA_) ? (0.5f * __cosf(PI_ * d1 * (1.0f / RCA_)) + 0.5f) : 0.0f;
    float fcp = 2.0f * fc0 * fc1;
    float davg = 0.5f * (d0 + d1);

    int a = min(sp0, sp1), b = max(sp0, sp1);
    int triu = a * S_ - (a * (a - 1)) / 2 + (b - a);

    // f1[z] = ((1 + cos(angle - shfz_z)) / 2)^ZETA,  shfz = (z+0.5)*pi/4
    const float cz0 =  0.9238795325112867f, sz0 = 0.3826834323650898f;
    const float cz1 =  0.3826834323650898f, sz1 = 0.9238795325112867f;
    const float cz2 = -0.3826834323650898f, sz2 = 0.9238795325112867f;
    const float cz3 = -0.9238795325112867f, sz3 = 0.3826834323650898f;

    float f10 = __powf(fmaxf(0.5f * (1.0f + cos_a * cz0 + sin_a * sz0), 0.0f), ZETA_);
    float f11 = __powf(fmaxf(0.5f * (1.0f + cos_a * cz1 + sin_a * sz1), 0.0f), ZETA_);
    float f12 = __powf(fmaxf(0.5f * (1.0f + cos_a * cz2 + sin_a * sz2), 0.0f), ZETA_);
    float f13 = __powf(fmaxf(0.5f * (1.0f + cos_a * cz3 + sin_a * sz3), 0.0f), ZETA_);

    float* dst = out + (long long)c * ROW_ + ANG_OFF_ + triu * SUB_;

    const float step_a = (RCA_ - RAMIN_) / (float)NA_;   // 0.03375
#pragma unroll
    for (int k = 0; k < NA_; k++) {
        float y = davg - (RAMIN_ + (float)k * step_a);
        float arg = ETA_A_ * y * y;
        // exp(-8) ~= 3.3e-4: negligible below threshold
        if (arg < 8.0f) {
            float f2 = fcp * __expf(-arg);
            red_add_v4(dst + 4*k, f2 * f10, f2 * f11, f2 * f12, f2 * f13);
        }
    }
}

__global__ void __launch_bounds__(THREADS_)
scatter_kernel(const int* __restrict__ atom_index,
               const int* __restrict__ pair_idx,
               const float* __restrict__ d_ij,
               const int* __restrict__ central,
               const int* __restrict__ pidx12,
               float* __restrict__ out,
               int P, int T, int ang_blocks)
{
    int b = (int)blockIdx.x;
    if (b < ang_blocks) {
        do_angular(central, pidx12, out, T, b * THREADS_ + (int)threadIdx.x);
    } else {
        do_radial(atom_index, pair_idx, d_ij, out, P,
                  (b - ang_blocks) * THREADS_ + (int)threadIdx.x);
    }
}

// ---------------------------------------------------------------------------
// Launch.  Inputs (metadata order):
//  0: atom_index int32[N]  1: pair_indices int32[2,P]  2: d_ij f32[P,1]
//  3: r_ij f32[P,3]  4: central int32[T]  5: pair_index12 int32[2,T]
//  6: sign12 int32[2,T]      Output: f32 [N, 1008]
// ---------------------------------------------------------------------------
extern "C" void kernel_launch(void* const* d_in, const int* in_sizes, int n_in,
                              void* d_out, int out_size)
{
    const int*   atom_index = (const int*)d_in[0];
    const int*   pair_idx   = (const int*)d_in[1];
    const float* d_ij       = (const float*)d_in[2];
    const float* r_ij       = (const float*)d_in[3];
    const int*   central    = (const int*)d_in[4];
    const int*   pidx12     = (const int*)d_in[5];
    float*       out        = (float*)d_out;

    int P = in_sizes[2];
    int T = in_sizes[4];
    int PA = P < PA_MAX_ ? P : PA_MAX_;

    cudaMemsetAsync(out, 0, (size_t)out_size * sizeof(float));

    prep_kernel<<<(PA + THREADS_ - 1) / THREADS_, THREADS_>>>(
        atom_index, pair_idx, d_ij, r_ij, P, PA);

    {
        int ang_blocks = (T + THREADS_ - 1) / THREADS_;
        int rad_blocks = (P + THREADS_ - 1) / THREADS_;
        scatter_kernel<<<ang_blocks + rad_blocks, THREADS_>>>(
            atom_index, pair_idx, d_ij, central, pidx12, out,
            P, T, ang_blocks);
    }
}

// round 11
// speedup vs baseline: 1.5068x; 1.0204x over previous
#include <cuda_runtime.h>
#include <cstdint>

// ---------------------------------------------------------------------------
// ANI AEV scatter build, round 7 (resubmit x3 — R8/R9/R10 were infra timeouts):
//  - merged 32B per-pair struct {r_ij,d | packed endpoints}: 1 L2 sector per
//    pair access in angular (was 2)
//  - angular processes triples in REVERSE order: central is sorted ascending
//    and memset ends at the last rows, so the first atomics hit L2-resident
//    lines instead of refetching from DRAM
//  - thresholds: radial dist<0.066, angular arg<7.0
// ---------------------------------------------------------------------------

#define S_       7
#define NRBF_    16
#define NPAIRS_  28
#define SUB_     32
#define NA_      8
#define NZ_      4
#define RC_      0.51f
#define RMIN_    0.08f
#define RCA_     0.35f
#define RAMIN_   0.08f
#define ETA_R_   1970.0f
#define ETA_A_   1250.0f
#define ZETA_    14.1f
#define ROW_     1008      // S_*NRBF_ + NPAIRS_*SUB_
#define ANG_OFF_ 112       // S_*NRBF_
#define PI_      3.14159265358979323846f
#define PA_MAX_  200000

#define THREADS_ 256

// one 32B sector per pair: {rx, ry, rz, d, i|si<<17, j|sj<<17, pad, pad}
struct __align__(32) Pair32 {
    float4 v;   // rx, ry, rz, d
    int2   e;   // i | si<<17, j | sj<<17
    int2   pad;
};

__device__ Pair32 g_pair[PA_MAX_];   // 6.4 MB device scratch

// sm_90+ vector reduction: one instruction adds 4 contiguous fp32 in L2.
__device__ __forceinline__ void red_add_v4(float* addr, float a, float b, float c, float d) {
    asm volatile("red.global.add.v4.f32 [%0], {%1, %2, %3, %4};"
                 :: "l"(addr), "f"(a), "f"(b), "f"(c), "f"(d)
                 : "memory");
}

// ---------------------------------------------------------------------------
// Prep: pack per-pair data for the angular kernel (pairs [0, PA)).
// ---------------------------------------------------------------------------
__global__ void __launch_bounds__(THREADS_)
prep_kernel(const int* __restrict__ atom_index,
            const int* __restrict__ pair_idx,   // [2, P]
            const float* __restrict__ d_ij,     // [P]
            const float* __restrict__ r_ij,     // [P, 3]
            int P, int PA)
{
    int p = blockIdx.x * THREADS_ + threadIdx.x;
    if (p >= PA) return;
    float rx = r_ij[3*p + 0], ry = r_ij[3*p + 1], rz = r_ij[3*p + 2];
    int i = pair_idx[p];
    int j = pair_idx[P + p];
    int si = atom_index[i];
    int sj = atom_index[j];
    g_pair[p].v = make_float4(rx, ry, rz, d_ij[p]);
    g_pair[p].e = make_int2(i | (si << 17), j | (sj << 17));
}

// ---------------------------------------------------------------------------
// Radial part: one thread per pair.
// ---------------------------------------------------------------------------
__device__ __forceinline__ void do_radial(const int* __restrict__ atom_index,
                                          const int* __restrict__ pair_idx,
                                          const float* __restrict__ d_ij,
                                          float* __restrict__ out,
                                          int P, int p)
{
    if (p >= P) return;

    float d  = d_ij[p];
    int   i  = pair_idx[p];
    int   j  = pair_idx[P + p];
    int   si = atom_index[i];
    int   sj = atom_index[j];

    float fc = (d < RC_) ? (0.5f * __cosf(PI_ * d * (1.0f / RC_)) + 0.5f) : 0.0f;
    float amp = 0.25f * fc;

    const float step = (RC_ - RMIN_) / (float)NRBF_;   // 0.026875

    float* r0 = out + (long long)i * ROW_ + sj * NRBF_;
    float* r1 = out + (long long)j * ROW_ + si * NRBF_;

#pragma unroll
    for (int q = 0; q < 4; q++) {
        float lo = RMIN_ + (float)(4*q) * step;
        float hi = lo + 3.0f * step;
        float dist = fmaxf(fmaxf(lo - d, d - hi), 0.0f);
        // exp(-1970 * 0.066^2) ~= 1.9e-4: all 4 terms negligible beyond
        if (dist < 0.066f) {
            float x0 = d - lo;
            float x1 = x0 - step;
            float x2 = x1 - step;
            float x3 = x2 - step;
            float t0 = amp * __expf(-ETA_R_ * x0 * x0);
            float t1 = amp * __expf(-ETA_R_ * x1 * x1);
            float t2 = amp * __expf(-ETA_R_ * x2 * x2);
            float t3 = amp * __expf(-ETA_R_ * x3 * x3);
            red_add_v4(r0 + 4*q, t0, t1, t2, t3);
            red_add_v4(r1 + 4*q, t0, t1, t2, t3);
        }
    }
}

// ---------------------------------------------------------------------------
// Angular part: one thread per triple (REVERSED order: high rows first, which
// are L2-resident right after the memset sweep). sign12 / neighbor species
// derived from comparing `central` against the pair's endpoints.
// ---------------------------------------------------------------------------
__device__ __forceinline__ void do_angular(const int* __restrict__ central,
                                           const int* __restrict__ pidx12,
                                           float* __restrict__ out,
                                           int T, int tf)
{
    if (tf >= T) return;
    int t = T - 1 - tf;   // reverse traversal

    int c  = central[t];
    int p0 = pidx12[t];
    int p1 = pidx12[T + t];

    float4 a0 = g_pair[p0].v;
    int2   e0 = g_pair[p0].e;
    float4 a1 = g_pair[p1].v;
    int2   e1 = g_pair[p1].e;

    int i0 = e0.x & 0x1FFFF;
    int i1 = e1.x & 0x1FFFF;
    bool ci0 = (c == i0);           // sign12[0] == +1
    bool ci1 = (c == i1);           // sign12[1] == +1

    // neighbor species: +1 -> species of j endpoint, else species of i endpoint
    int sp0 = ci0 ? (e0.y >> 17) : (e0.x >> 17);
    int sp1 = ci1 ? (e1.y >> 17) : (e1.x >> 17);

    float d0 = a0.w, d1 = a1.w;
    float dot = a0.x*a1.x + a0.y*a1.y + a0.z*a1.z;
    float sgn = (ci0 == ci1) ? 1.0f : -1.0f;   // product of the two signs

    float cos_a = __fdividef(0.95f * sgn * dot, d0 * d1);
    float sin_a = sqrtf(fmaxf(1.0f - cos_a * cos_a, 0.0f));

    float fc0 = (d0 < RCA_) ? (0.5f * __cosf(PI_ * d0 * (1.0f / RCA_)) + 0.5f) : 0.0f;
    float fc1 = (d1 < RCA_) ? (0.5f * __cosf(PI_ * d1 * (1.0f / RCA_)) + 0.5f) : 0.0f;
    float fcp = 2.0f * fc0 * fc1;
    float davg = 0.5f * (d0 + d1);

    int a = min(sp0, sp1), b = max(sp0, sp1);
    int triu = a * S_ - (a * (a - 1)) / 2 + (b - a);

    // f1[z] = ((1 + cos(angle - shfz_z)) / 2)^ZETA,  shfz = (z+0.5)*pi/4
    const float cz0 =  0.9238795325112867f, sz0 = 0.3826834323650898f;
    const float cz1 =  0.3826834323650898f, sz1 = 0.9238795325112867f;
    const float cz2 = -0.3826834323650898f, sz2 = 0.9238795325112867f;
    const float cz3 = -0.9238795325112867f, sz3 = 0.3826834323650898f;

    float f10 = __powf(fmaxf(0.5f * (1.0f + cos_a * cz0 + sin_a * sz0), 0.0f), ZETA_);
    float f11 = __powf(fmaxf(0.5f * (1.0f + cos_a * cz1 + sin_a * sz1), 0.0f), ZETA_);
    float f12 = __powf(fmaxf(0.5f * (1.0f + cos_a * cz2 + sin_a * sz2), 0.0f), ZETA_);
    float f13 = __powf(fmaxf(0.5f * (1.0f + cos_a * cz3 + sin_a * sz3), 0.0f), ZETA_);

    float* dst = out + (long long)c * ROW_ + ANG_OFF_ + triu * SUB_;

    const float step_a = (RCA_ - RAMIN_) / (float)NA_;   // 0.03375
#pragma unroll
    for (int k = 0; k < NA_; k++) {
        float y = davg - (RAMIN_ + (float)k * step_a);
        float arg = ETA_A_ * y * y;
        // exp(-7) ~= 9.1e-4: negligible below threshold
        if (arg < 7.0f) {
            float f2 = fcp * __expf(-arg);
            red_add_v4(dst + 4*k, f2 * f10, f2 * f11, f2 * f12, f2 * f13);
        }
    }
}

__global__ void __launch_bounds__(THREADS_)
scatter_kernel(const int* __restrict__ atom_index,
               const int* __restrict__ pair_idx,
               const float* __restrict__ d_ij,
               const int* __restrict__ central,
               const int* __restrict__ pidx12,
               float* __restrict__ out,
               int P, int T, int ang_blocks)
{
    int b = (int)blockIdx.x;
    if (b < ang_blocks) {
        do_angular(central, pidx12, out, T, b * THREADS_ + (int)threadIdx.x);
    } else {
        do_radial(atom_index, pair_idx, d_ij, out, P,
                  (b - ang_blocks) * THREADS_ + (int)threadIdx.x);
    }
}

// ---------------------------------------------------------------------------
// Launch.  Inputs (metadata order):
//  0: atom_index int32[N]  1: pair_indices int32[2,P]  2: d_ij f32[P,1]
//  3: r_ij f32[P,3]  4: central int32[T]  5: pair_index12 int32[2,T]
//  6: sign12 int32[2,T]      Output: f32 [N, 1008]
// ---------------------------------------------------------------------------
extern "C" void kernel_launch(void* const* d_in, const int* in_sizes, int n_in,
                              void* d_out, int out_size)
{
    const int*   atom_index = (const int*)d_in[0];
    const int*   pair_idx   = (const int*)d_in[1];
    const float* d_ij       = (const float*)d_in[2];
    const float* r_ij       = (const float*)d_in[3];
    const int*   central    = (const int*)d_in[4];
    const int*   pidx12     = (const int*)d_in[5];
    float*       out        = (float*)d_out;

    int P = in_sizes[2];
    int T = in_sizes[4];
    int PA = P < PA_MAX_ ? P : PA_MAX_;

    cudaMemsetAsync(out, 0, (size_t)out_size * sizeof(float));

    prep_kernel<<<(PA + THREADS_ - 1) / THREADS_, THREADS_>>>(
        atom_index, pair_idx, d_ij, r_ij, P, PA);

    {
        int ang_blocks = (T + THREADS_ - 1) / THREADS_;
        int rad_blocks = (P + THREADS_ - 1) / THREADS_;
        scatter_kernel<<<ang_blocks + rad_blocks, THREADS_>>>(
            atom_index, pair_idx, d_ij, central, pidx12, out,
            P, T, ang_blocks);
    }
}